// round 6
// baseline (speedup 1.0000x reference)
#include <cuda_runtime.h>
#include <stdint.h>

// RadialTokenizer — streaming redesign.
// Per (b,c) image: quantize to integers [127,254]; per 16 radial rings:
// mean/std/median via exact 128-bin histograms.
// Block = one (b,c); warp streams a contiguous 8192-px slab with float4
// loads; ring id from u8 table; per-warp u16 histogram keyed by
// ring*128+bin with match_any leader election (no atomics).

#define HH 256
#define WW 256
#define NR 16
#define NPX (HH * WW)

__device__ __align__(128) uint8_t g_ring[NPX];   // ring id per pixel, 16 = none

// ring i <=> 64*i^2 < d2 <= 64*(i+1)^2 ; center pixel excluded.
__device__ __forceinline__ int ring_of(int x, int y) {
    int dx = x - 128, dy = y - 128;
    int d2 = dx * dx + dy * dy;
    if (d2 == 0 || d2 > 16384) return -1;
    int i = (int)(__fmul_rn(sqrtf((float)d2), 0.125f) + 0.999f) - 1;
    if (i < 0) i = 0;
    while (i > 0 && 64 * i * i >= d2) i--;
    while (d2 > 64 * (i + 1) * (i + 1)) i++;
    return i;
}

__global__ void k_ringtab() {
    int x = threadIdx.x, y = blockIdx.x;
    int r = ring_of(x, y);
    g_ring[y * WW + x] = (uint8_t)(r < 0 ? 16 : r);
}

// ---------------- main kernel ----------------
// 256 threads, 36KB smem -> 6 blocks/SM (grid 768 fully resident, 1 wave).

__global__ void __launch_bounds__(256, 6) k_main(const float* __restrict__ img,
                                                 float* __restrict__ out) {
    __shared__ __align__(16) uint16_t h16[8][2048];   // per-warp hists, 32KB
    __shared__ __align__(16) uint16_t hfin[2048];     // block hist, 4KB

    const int tid  = threadIdx.x;
    const int lane = tid & 31;
    const int w    = tid >> 5;
    const int bc   = blockIdx.x;
    const float* __restrict__ ip = img + (size_t)bc * NPX;

    // zero this warp's histogram (4KB)
    {
        uint4* hz = (uint4*)h16[w];
        uint4 z; z.x = z.y = z.z = z.w = 0u;
        #pragma unroll
        for (int j = 0; j < 8; j++) hz[j * 32 + lane] = z;
    }
    __syncwarp();

    uint16_t* h = h16[w];
    const unsigned lt = (1u << lane) - 1u;

    // stream 8192 px: 64 iters x 128 px (lane handles 4 consecutive px)
    const int base = w * 8192 + lane * 4;           // multiple of 4
    const float4*   __restrict__ ipv = (const float4*)ip;
    const uint32_t* __restrict__ tbv = (const uint32_t*)g_ring;

    float4   v  = __ldcs(&ipv[base >> 2]);
    uint32_t tb = tbv[base >> 2];

    for (int it = 0; it < 64; it++) {
        int nx = (it < 63) ? (it + 1) : 63;          // clamp: last prefetch harmless
        int pxn = (base + nx * 128) >> 2;
        float4   vn  = __ldcs(&ipv[pxn]);
        uint32_t tbn = tbv[pxn];

        float xs0 = v.x, xs1 = v.y, xs2 = v.z, xs3 = v.w;
        float xv[4] = {xs0, xs1, xs2, xs3};
        #pragma unroll
        for (int j = 0; j < 4; j++) {
            // bit-identical to reference: (x*0.5)+0.5 (single rounding, exact
            // mul) then *255, then floor.
            float t = __fmul_rn(__fmaf_rn(xv[j], 0.5f, 0.5f), 255.0f);
            int val = __float2int_rd(t);             // 127..254
            int rb  = (tb >> (8 * j)) & 0xFF;        // 0..16
            int key = rb * 128 + (val - 127);        // 0..2175
            unsigned m = __match_any_sync(0xffffffffu, key);
            int cnt = __popc(m);
            if ((m & lt) == 0 && key < 2048)         // leader, valid ring
                h[key] = (uint16_t)(h[key] + cnt);
        }
        v = vn; tb = tbn;
    }
    __syncthreads();

    // block reduce: thread t sums keys {t + k*256} over the 8 warp hists
    #pragma unroll
    for (int k = 0; k < 8; k++) {
        int key = tid + k * 256;
        uint32_t s = 0;
        #pragma unroll
        for (int ww = 0; ww < 8; ww++) s += h16[ww][key];
        hfin[key] = (uint16_t)s;
    }
    __syncthreads();

    // stats: warp w handles rings w and w+8; lane owns bins 4l..4l+3
    const int b = bc / 3, c = bc - b * 3;
    #pragma unroll
    for (int rr = 0; rr < 2; rr++) {
        const int ring = w + rr * 8;
        ushort4 q = ((const ushort4*)hfin)[ring * 32 + lane];
        int h0 = q.x, h1 = q.y, h2 = q.z, h3 = q.w;

        const int b0 = lane * 4;
        int sl  = h0 + h1 + h2 + h3;
        int sb  = h0 * b0 + h1 * (b0 + 1) + h2 * (b0 + 2) + h3 * (b0 + 3);
        int sb2 = h0 * b0 * b0 + h1 * (b0 + 1) * (b0 + 1)
                + h2 * (b0 + 2) * (b0 + 2) + h3 * (b0 + 3) * (b0 + 3);

        int sumb  = __reduce_add_sync(0xffffffffu, sb);
        int sumb2 = __reduce_add_sync(0xffffffffu, sb2);

        int sc = sl;
        #pragma unroll
        for (int d = 1; d < 32; d <<= 1) {
            int t2 = __shfl_up_sync(0xffffffffu, sc, d);
            if (lane >= d) sc += t2;
        }
        int n  = __shfl_sync(0xffffffffu, sc, 31);
        int cb = sc - sl;

        int k1 = (n - 1) >> 1, k2 = n >> 1;
        int c1 = 1 << 30, c2 = 1 << 30;
        {
            int t1 = k1 + 1;
            if (cb < t1 && t1 <= sc) {
                if      (cb + h0 >= t1)           c1 = b0;
                else if (cb + h0 + h1 >= t1)      c1 = b0 + 1;
                else if (cb + h0 + h1 + h2 >= t1) c1 = b0 + 2;
                else                              c1 = b0 + 3;
            }
            int t2r = k2 + 1;
            if (cb < t2r && t2r <= sc) {
                if      (cb + h0 >= t2r)           c2 = b0;
                else if (cb + h0 + h1 >= t2r)      c2 = b0 + 1;
                else if (cb + h0 + h1 + h2 >= t2r) c2 = b0 + 2;
                else                               c2 = b0 + 3;
            }
        }
        int m1 = __reduce_min_sync(0xffffffffu, c1);
        int m2 = __reduce_min_sync(0xffffffffu, c2);

        if (lane == 0) {
            double dn = (double)n;
            double mb = (double)sumb / dn;
            double mean = 127.0 + mb;
            double var = (double)sumb2 / dn - mb * mb;
            double sd = sqrt(var > 0.0 ? var : 0.0);
            double med = 127.0 + 0.5 * (double)(m1 + m2);
            int o = b * (NR * 9) + ring * 9 + c;
            out[o]     = (float)mean;
            out[o + 3] = (float)sd;
            out[o + 6] = (float)med;
        }
    }
}

extern "C" void kernel_launch(void* const* d_in, const int* in_sizes, int n_in,
                              void* d_out, int out_size) {
    const float* img = (const float*)d_in[0];
    float* out = (float*)d_out;

    k_ringtab<<<HH, WW>>>();
    k_main<<<768, 256>>>(img, out);
}

// round 7
// speedup vs baseline: 3.2831x; 3.2831x over previous
#include <cuda_runtime.h>
#include <stdint.h>

// RadialTokenizer — gather + cp.async deep pipeline.
// Per (b,c) image: quantize floor((x*0.5+0.5)*255) -> [127,254] (128 bins);
// 16 radial rings: mean/std/median from exact per-ring 128-bin histograms.
// Warp = 2 ring-pairs (rings w,15-w,w+4,11-w): identical work per warp.
// Pixels gathered with per-lane 4B cp.async into double-buffered smem
// (latency hidden by async depth, not registers). Per-lane byte histograms
// (bank==lane, conflict-free, no atomics). Ring lists padded to 512 with
// sentinel offset 0; sentinel counts subtracted exactly in the epilogue.

#define HH 256
#define WW 256
#define NR 16
#define MAXPIX 60416   // ~51472 real + per-ring pad to 512 multiples

__device__ __align__(128) uint16_t g_off[MAXPIX];
__device__ int g_ringbase[NR + 1];   // starts, multiples of 512 entries
__device__ int g_ringlen[NR];        // true pixel counts
__device__ int g_ringpad[NR];        // padded - true
__device__ int g_rowcnt[HH * NR];
__device__ int g_rowstart[HH * NR];

// ring i <=> 64*i^2 < d2 <= 64*(i+1)^2 ; center pixel excluded.
__device__ __forceinline__ int ring_of(int x, int y) {
    int dx = x - 128, dy = y - 128;
    int d2 = dx * dx + dy * dy;
    if (d2 == 0 || d2 > 16384) return -1;
    int i = (int)(__fmul_rn(sqrtf((float)d2), 0.125f) + 0.999f) - 1;
    if (i < 0) i = 0;
    while (i > 0 && 64 * i * i >= d2) i--;
    while (d2 > 64 * (i + 1) * (i + 1)) i++;
    return i;
}

// ---------------- init kernels (deterministic, every launch) ----------------

__global__ void k_count() {
    __shared__ int cnt[NR];
    int x = threadIdx.x, y = blockIdx.x;
    int lane = x & 31;
    if (x < NR) cnt[x] = 0;
    __syncthreads();
    int r = ring_of(x, y);
    unsigned m = __match_any_sync(0xffffffffu, r);
    if (r >= 0 && (m & ((1u << lane) - 1)) == 0)
        atomicAdd(&cnt[r], __popc(m));
    __syncthreads();
    if (x < NR) g_rowcnt[y * NR + x] = cnt[x];
}

__global__ void k_prefix() {
    int t = threadIdx.x;
    __shared__ int tot[NR];
    __shared__ int base[NR];
    if (t < NR) {
        int s = 0;
        for (int y = 0; y < HH; y++) s += g_rowcnt[y * NR + t];
        tot[t] = s;
    }
    __syncthreads();
    if (t == 0) {
        int run = 0;
        for (int r = 0; r < NR; r++) {
            base[r] = run;
            g_ringbase[r] = run;
            g_ringlen[r] = tot[r];
            int pn = (tot[r] + 511) & ~511;
            g_ringpad[r] = pn - tot[r];
            run += pn;
        }
        g_ringbase[NR] = run;
    }
    __syncthreads();
    if (t < NR) {
        int run = base[t];
        for (int y = 0; y < HH; y++) {
            g_rowstart[y * NR + t] = run;
            run += g_rowcnt[y * NR + t];
        }
    }
}

__global__ void k_scatter() {
    __shared__ int wcnt[8][NR];
    __shared__ int wbase[8][NR];
    int x = threadIdx.x, y = blockIdx.x;
    int lane = x & 31, w = x >> 5;
    int r = ring_of(x, y);
    unsigned m = __match_any_sync(0xffffffffu, r);
    int rank = __popc(m & ((1u << lane) - 1));
    if (x < 8 * NR) ((int*)wcnt)[x] = 0;
    __syncthreads();
    if (r >= 0 && rank == 0) wcnt[w][r] = __popc(m);
    __syncthreads();
    if (x < NR) {
        int run = 0;
        #pragma unroll
        for (int ww = 0; ww < 8; ww++) { wbase[ww][x] = run; run += wcnt[ww][x]; }
    }
    __syncthreads();
    if (r >= 0)
        g_off[g_rowstart[y * NR + r] + wbase[w][r] + rank] = (uint16_t)(y * WW + x);
}

// fill padding entries with sentinel offset 0
__global__ void k_pad() {
    int r = blockIdx.x;
    int s = g_ringbase[r] + g_ringlen[r];
    int e = g_ringbase[r] + g_ringlen[r] + g_ringpad[r];
    for (int i = s + threadIdx.x; i < e; i += blockDim.x)
        g_off[i] = 0;
}

// ---------------- main kernel ----------------
// Grid 768 (one block per (b,c)), 4 warps. smem: 4x4KB hist + 4x4KB staging
// = 32KB -> 7 blocks/SM, single fully-resident wave.
// Hist byte addr = ((bin<<5)&0xF80) | (lane<<2) | (bin&3)  -> bank == lane.

__global__ void __launch_bounds__(128, 7) k_main(const float* __restrict__ img,
                                                 float* __restrict__ out) {
    __shared__ uint8_t hist[4][4096];
    __shared__ __align__(16) float stage[4][1024];   // 2 x 512-px buffers/warp

    const int lane = threadIdx.x & 31;
    const int w    = threadIdx.x >> 5;
    const int bc   = blockIdx.x;
    const float* __restrict__ ip = img + (size_t)bc * (HH * WW);

    uint8_t* h = hist[w];
    const int hb_lane = lane << 2;
    const int b = bc / 3, c = bc - b * 3;
    const uint32_t sbuf = (uint32_t)__cvta_generic_to_shared(&stage[w][0]);

    // sentinel pixel (offset 0) bin, for pad subtraction
    float t0 = __fmul_rn(__fmaf_rn(__ldg(ip), 0.5f, 0.5f), 255.0f);
    const int bin0 = __float2int_rd(t0) - 127;

    #pragma unroll
    for (int rq = 0; rq < 4; rq++) {
        // rings: w, 15-w, w+4, 11-w  (two balanced pairs -> 64 area units)
        const int p    = (rq & 2) ? (w + 4) : w;
        const int ring = (rq & 1) ? (15 - p) : p;

        // zero this warp's 4KB histogram
        {
            uint4* hz = (uint4*)h;
            uint4 z; z.x = z.y = z.z = z.w = 0u;
            #pragma unroll
            for (int j = 0; j < 8; j++) hz[j * 32 + lane] = z;
        }
        __syncwarp();

        const int start = g_ringbase[ring];        // multiple of 512
        const int n     = g_ringlen[ring];
        const int pad   = g_ringpad[ring];
        const int C     = (n + pad) >> 9;          // full 512-px chunks
        const uint32_t* __restrict__ offs32 = (const uint32_t*)(g_off + start);

        // ---- async gather pipeline ----
        // issue chunk 0
        {
            #pragma unroll
            for (int j = 0; j < 8; j++) {
                uint32_t ow = offs32[j * 32 + lane];
                uint32_t d = sbuf + ((j * 64 + lane * 2) << 2);
                const float* g0 = ip + (ow & 0xFFFFu);
                const float* g1 = ip + (ow >> 16);
                asm volatile("cp.async.ca.shared.global [%0], [%1], 4;" :: "r"(d), "l"(g0));
                asm volatile("cp.async.ca.shared.global [%0], [%1], 4;" :: "r"(d + 4), "l"(g1));
            }
            asm volatile("cp.async.commit_group;");
        }

        for (int cc = 0; cc < C; cc++) {
            if (cc + 1 < C) {
                int cb2 = ((cc + 1) << 9) >> 1;
                uint32_t dst = sbuf + (((cc + 1) & 1) << 11);
                #pragma unroll
                for (int j = 0; j < 8; j++) {
                    uint32_t ow = offs32[cb2 + j * 32 + lane];
                    uint32_t d = dst + ((j * 64 + lane * 2) << 2);
                    const float* g0 = ip + (ow & 0xFFFFu);
                    const float* g1 = ip + (ow >> 16);
                    asm volatile("cp.async.ca.shared.global [%0], [%1], 4;" :: "r"(d), "l"(g0));
                    asm volatile("cp.async.ca.shared.global [%0], [%1], 4;" :: "r"(d + 4), "l"(g1));
                }
                asm volatile("cp.async.commit_group;");
                asm volatile("cp.async.wait_group 1;");
            } else {
                asm volatile("cp.async.wait_group 0;");
            }
            __syncwarp();

            // consume buf[cc&1]: 512 px, 4 conflict-free LDS.128 per lane
            const float4* bv = (const float4*)&stage[w][(cc & 1) << 9];
            #pragma unroll
            for (int k = 0; k < 4; k++) {
                float4 q = bv[lane + 32 * k];
                float xv[4] = {q.x, q.y, q.z, q.w};
                #pragma unroll
                for (int j = 0; j < 4; j++) {
                    // bit-identical to ref: fma(x,0.5,0.5) exact-mul single
                    // rounding == (x*0.5)+0.5; then unfused *255; floor.
                    float t = __fmul_rn(__fmaf_rn(xv[j], 0.5f, 0.5f), 255.0f);
                    int bin = __float2int_rd(t) - 127;
                    h[((bin << 5) & 0xF80) | hb_lane | (bin & 3)] += 1;
                }
            }
            __syncwarp();
        }

        // ---- reduce: lane l owns bins 4l..4l+3 ----
        const uint32_t* hw = (const uint32_t*)h;
        uint32_t a02 = 0, a13 = 0;
        #pragma unroll
        for (int jj = 0; jj < 32; jj++) {
            int j = (jj + lane) & 31;
            uint32_t vv = hw[lane * 32 + j];
            a02 += vv & 0x00FF00FFu;
            a13 += (vv >> 8) & 0x00FF00FFu;
        }
        int h0 = (int)(a02 & 0xFFFFu), h2 = (int)(a02 >> 16);
        int h1 = (int)(a13 & 0xFFFFu), h3 = (int)(a13 >> 16);

        // subtract sentinel-pad counts from bin0
        if ((bin0 >> 2) == lane) {
            int q = bin0 & 3;
            if (q == 0) h0 -= pad;
            else if (q == 1) h1 -= pad;
            else if (q == 2) h2 -= pad;
            else h3 -= pad;
        }

        const int b0 = lane * 4;
        int sl  = h0 + h1 + h2 + h3;
        int sb  = h0 * b0 + h1 * (b0 + 1) + h2 * (b0 + 2) + h3 * (b0 + 3);
        int sb2 = h0 * b0 * b0 + h1 * (b0 + 1) * (b0 + 1)
                + h2 * (b0 + 2) * (b0 + 2) + h3 * (b0 + 3) * (b0 + 3);

        int sumb  = __reduce_add_sync(0xffffffffu, sb);
        int sumb2 = __reduce_add_sync(0xffffffffu, sb2);

        int sc = sl;
        #pragma unroll
        for (int d = 1; d < 32; d <<= 1) {
            int t2 = __shfl_up_sync(0xffffffffu, sc, d);
            if (lane >= d) sc += t2;
        }
        int cb = sc - sl;   // == n prefix; total == n

        int k1 = (n - 1) >> 1, k2 = n >> 1;
        int c1 = 1 << 30, c2 = 1 << 30;
        {
            int t1 = k1 + 1;
            if (cb < t1 && t1 <= sc) {
                if      (cb + h0 >= t1)           c1 = b0;
                else if (cb + h0 + h1 >= t1)      c1 = b0 + 1;
                else if (cb + h0 + h1 + h2 >= t1) c1 = b0 + 2;
                else                              c1 = b0 + 3;
            }
            int t2r = k2 + 1;
            if (cb < t2r && t2r <= sc) {
                if      (cb + h0 >= t2r)           c2 = b0;
                else if (cb + h0 + h1 >= t2r)      c2 = b0 + 1;
                else if (cb + h0 + h1 + h2 >= t2r) c2 = b0 + 2;
                else                               c2 = b0 + 3;
            }
        }
        int m1 = __reduce_min_sync(0xffffffffu, c1);
        int m2 = __reduce_min_sync(0xffffffffu, c2);

        if (lane == 0) {
            double dn = (double)n;
            double mb = (double)sumb / dn;
            double mean = 127.0 + mb;
            double var = (double)sumb2 / dn - mb * mb;
            double sd = sqrt(var > 0.0 ? var : 0.0);
            double med = 127.0 + 0.5 * (double)(m1 + m2);
            int o = b * (NR * 9) + ring * 9 + c;
            out[o]     = (float)mean;
            out[o + 3] = (float)sd;
            out[o + 6] = (float)med;
        }
        __syncwarp();
    }
}

extern "C" void kernel_launch(void* const* d_in, const int* in_sizes, int n_in,
                              void* d_out, int out_size) {
    const float* img = (const float*)d_in[0];
    float* out = (float*)d_out;

    k_count<<<HH, WW>>>();
    k_prefix<<<1, 32>>>();
    k_scatter<<<HH, WW>>>();
    k_pad<<<NR, 256>>>();

    k_main<<<768, 128>>>(img, out);
}